// round 10
// baseline (speedup 1.0000x reference)
#include <cuda_runtime.h>
#include <cuda_bf16.h>

// x: [20000, 512] f32 ; weight: [50] f32 ; idx: [50,2000] int32
// out[c*R + r] = x[idx[r], c] * w[r/2000],  R = 100000, C = 512
#define N_FEATURE 20000
#define N_CELL    512
#define N_CT      50
#define M_PER_CT  2000
#define R_TOTAL   (N_CT * M_PER_CT)     // 100000

#define TILE_R 32
#define TILE_C 64

// One 32r x 64c tile per block; grid (3125, 8) = 25000 blocks -> ~21 waves,
// negligible wave-quantization tail (v7's 4.2-wave grid left ~8% on the floor
// of the LTS cap during its ragged last wave). Latency overlap comes from the
// 8 resident blocks per SM instead of an intra-block cp.async ring.
//
// SMEM tile: row-major [row][granule16B], 16 granules/row.
// Granule (row, g) at slot s = g ^ ((row>>2) & 7).
//  - cp.async: half-warp per row -> 16 distinct slots, 256B dense gmem read.
//  - store-phase scalar LDS: banks 4*(c4^r4)+dd all distinct per warp.
//  - STG.128 streaming: each 8-lane octet writes 128B contiguous.
__global__ __launch_bounds__(256, 8)
void celltype_scale_transpose_v8(const float4* __restrict__ x4,
                                 const float*  __restrict__ w,
                                 const int*    __restrict__ idx,
                                 float*        __restrict__ out)
{
    __shared__ float buf[TILE_R * TILE_C];           // 8 KB

    const int r0  = blockIdx.x * TILE_R;             // 3125 r-tiles
    const int c0  = blockIdx.y * TILE_C;             // 8 c-tiles
    const int c0q = c0 >> 2;
    const int tid = threadIdx.x;
    const int hw  = tid >> 4;                        // half-warp id 0..15
    const int g   = tid & 15;                        // granule 0..15

    // ---- async gather: 2 x cp.async.cg per thread ----
    #pragma unroll
    for (int i = 0; i < 2; i++) {
        const int row  = 16 * i + hw;                // 0..31, half-warp uniform
        const int srow = __ldg(&idx[r0 + row]);      // broadcast
        const int s    = g ^ ((row >> 2) & 7);       // swizzled granule slot
        const float4* src = &x4[(size_t)srow * (N_CELL / 4) + c0q + g];
        unsigned dst = (unsigned)__cvta_generic_to_shared(&buf[row * TILE_C + 4 * s]);
        asm volatile("cp.async.cg.shared.global [%0], [%1], 16;\n"
                     :: "r"(dst), "l"(src));
    }
    asm volatile("cp.async.commit_group;\n");
    asm volatile("cp.async.wait_group 0;\n");
    __syncthreads();

    // ---- scale + transpose-store ----
    const int r4   = tid & 7;                        // r-granule 0..7
    const int chi  = tid >> 3;                       // c base 0..31
    const int c4g0 = chi >> 2;
    const int dd   = chi & 3;

    const float* b  = buf + 4 * r4 * TILE_C + dd;    // rows 4r4..4r4+3
    const float wv  = w[(unsigned)(r0 + 4 * r4) / M_PER_CT];  // 4-aligned group
    float* outb = out + (size_t)(c0 + chi) * R_TOTAL + r0 + 4 * r4;

    #pragma unroll
    for (int i = 0; i < 2; i++) {
        const int s = ((c4g0 + 8 * i) ^ r4) * 4;     // swizzled granule offset
        float4 v;
        v.x = b[0 * TILE_C + s] * wv;
        v.y = b[1 * TILE_C + s] * wv;
        v.z = b[2 * TILE_C + s] * wv;
        v.w = b[3 * TILE_C + s] * wv;
        __stcs((float4*)(outb + (size_t)(32 * i) * R_TOTAL), v);
    }
}

extern "C" void kernel_launch(void* const* d_in, const int* in_sizes, int n_in,
                              void* d_out, int out_size)
{
    const float* x   = nullptr;
    const float* w   = nullptr;
    const int*   idx = nullptr;
    for (int i = 0; i < n_in; i++) {
        if (in_sizes[i] == N_FEATURE * N_CELL)      x   = (const float*)d_in[i];
        else if (in_sizes[i] == N_CT)               w   = (const float*)d_in[i];
        else if (in_sizes[i] == R_TOTAL)            idx = (const int*)d_in[i];
    }
    float* out = (float*)d_out;

    dim3 grid(R_TOTAL / TILE_R, N_CELL / TILE_C);   // (3125, 8) = 25000 blocks
    celltype_scale_transpose_v8<<<grid, 256>>>((const float4*)x, w, idx, out);
}

// round 13
// speedup vs baseline: 1.3329x; 1.3329x over previous
#include <cuda_runtime.h>
#include <cuda_bf16.h>

// x: [20000, 512] f32 ; weight: [50] f32 ; idx: [50,2000] int32
// out[c*R + r] = x[idx[r], c] * w[r/2000],  R = 100000, C = 512
#define N_FEATURE 20000
#define N_CELL    512
#define N_CT      50
#define M_PER_CT  2000
#define R_TOTAL   (N_CT * M_PER_CT)     // 100000

#define TILE_R 32
#define TILE_C 32
#define NITER  5                        // r-tiles per block; 3125 = 5 * 625
#define STAGES 3                        // ring buffer depth

// v7 pipeline structure (best so far) with TILE_C halved to 32:
//  - grid (625,16)=10000 blocks -> 8.45 waves, halved wave-tail quantum
//  - per-c-group read set = 20000 rows x 128B = 2.5 MB, L2-hot
// SMEM tile: row-major [row][granule16B], 8 granules/row (4 KB/stage).
// Granule (row, g) at slot s = g ^ ((row>>2) & 7).
//  - cp.async: quarter-warp per row -> words 4*(g^w)+k hit all 32 banks,
//    128B dense gmem read per row.
//  - store-phase scalar LDS: banks 4*(w^r4)+dd all distinct per warp.
//  - STG.128 streaming: each 8-lane octet writes 128B contiguous.
__device__ __forceinline__ void issue_tile(const float4* __restrict__ x4,
                                           const int* __restrict__ idx,
                                           float* __restrict__ buf,
                                           int r0, int c0q, int row, int g)
{
    const int srow = __ldg(&idx[r0 + row]);          // quarter-warp broadcast
    const int s    = g ^ ((row >> 2) & 7);           // swizzled granule slot
    const float4* src = &x4[(size_t)srow * (N_CELL / 4) + c0q + g];
    unsigned dst = (unsigned)__cvta_generic_to_shared(&buf[row * TILE_C + 4 * s]);
    asm volatile("cp.async.cg.shared.global [%0], [%1], 16;\n"
                 :: "r"(dst), "l"(src));
    asm volatile("cp.async.commit_group;\n");
}

__global__ __launch_bounds__(256, 8)
void celltype_scale_transpose_v9(const float4* __restrict__ x4,
                                 const float*  __restrict__ w,
                                 const int*    __restrict__ idx,
                                 float*        __restrict__ out)
{
    __shared__ float buf[STAGES][TILE_R * TILE_C];   // 3 x 4 KB = 12 KB

    const int rbase = blockIdx.x * (TILE_R * NITER); // 625 groups of 160 rows
    const int c0    = blockIdx.y * TILE_C;           // 16 c-tiles
    const int c0q   = c0 >> 2;
    const int tid   = threadIdx.x;
    const int row   = tid >> 3;                      // 0..31 (one row/thread)
    const int g     = tid & 7;                       // granule 0..7

    // Store-phase invariants:
    const int r4   = tid & 7;                        // r-granule 0..7
    const int chi  = tid >> 3;                       // c 0..31
    const int c4g0 = chi >> 2;
    const int dd   = chi & 3;

    // Prologue: two tiles in flight.
    issue_tile(x4, idx, buf[0], rbase,          c0q, row, g);
    issue_tile(x4, idx, buf[1], rbase + TILE_R, c0q, row, g);

    #pragma unroll
    for (int t = 0; t < NITER; t++) {
        const int r0 = rbase + t * TILE_R;

        // Wait for tile t's group. Pending: {t, t+1} (or {t} at the end).
        if (t + 1 < NITER) asm volatile("cp.async.wait_group 1;\n");
        else               asm volatile("cp.async.wait_group 0;\n");
        // Single barrier: tile t visible to all threads AND everyone done
        // reading tile t-1 (the buffer tile t+2 overwrites). 3-stage ring.
        __syncthreads();

        // Kick off tile t+2 before consuming t: overlap its gathered reads
        // with this iteration's store stream.
        if (t + 2 < NITER)
            issue_tile(x4, idx, buf[(t + 2) % STAGES], r0 + 2 * TILE_R, c0q, row, g);

        // ---- scale + transpose-store from buf[t % STAGES] ----
        const float* b  = buf[t % STAGES] + 4 * r4 * TILE_C + dd;  // rows 4r4..+3
        const float wv  = w[(unsigned)(r0 + 4 * r4) / M_PER_CT];   // 4-aligned
        const int s = (c4g0 ^ r4) * 4;                // swizzled granule offset
        float4 v;
        v.x = b[0 * TILE_C + s] * wv;
        v.y = b[1 * TILE_C + s] * wv;
        v.z = b[2 * TILE_C + s] * wv;
        v.w = b[3 * TILE_C + s] * wv;
        __stcs((float4*)&out[(size_t)(c0 + chi) * R_TOTAL + r0 + 4 * r4], v);
        // No second barrier (covered by next iteration's post-wait sync).
    }
}

extern "C" void kernel_launch(void* const* d_in, const int* in_sizes, int n_in,
                              void* d_out, int out_size)
{
    const float* x   = nullptr;
    const float* w   = nullptr;
    const int*   idx = nullptr;
    for (int i = 0; i < n_in; i++) {
        if (in_sizes[i] == N_FEATURE * N_CELL)      x   = (const float*)d_in[i];
        else if (in_sizes[i] == N_CT)               w   = (const float*)d_in[i];
        else if (in_sizes[i] == R_TOTAL)            idx = (const int*)d_in[i];
    }
    float* out = (float*)d_out;

    dim3 grid(R_TOTAL / (TILE_R * NITER), N_CELL / TILE_C);   // (625, 16)
    celltype_scale_transpose_v9<<<grid, 256>>>((const float4*)x, w, idx, out);
}

// round 17
// speedup vs baseline: 1.4584x; 1.0942x over previous
#include <cuda_runtime.h>
#include <cuda_bf16.h>

// x: [20000, 512] f32 ; weight: [50] f32 ; idx: [50,2000] int32
// out[c*R + r] = x[idx[r], c] * w[r/2000],  R = 100000, C = 512
#define N_FEATURE 20000
#define N_CELL    512
#define N_CT      50
#define M_PER_CT  2000
#define R_TOTAL   (N_CT * M_PER_CT)     // 100000

#define TILE_R 32
#define TILE_C 64
#define NITER  5                        // r-tiles per block; 3125 = 5 * 625
#define STAGES 3                        // ring buffer depth

// Final kernel (v7): measured optimum of the family.
//  - 32r x 64c tiles, 5 per block, 3-stage cp.async ring, ONE barrier/iter.
//  - Rides the HW LTS cap (~6300 B/cyc): 410 MB compulsory L2 crossings
//    => ~37 us floor; this kernel measures 39.1 us (ncu).
//  - v8 (no pipeline) and v9 (TILE_C=32) both regressed; tile growth would
//    drop occupancy below 8 blocks/SM.
// SMEM tile: row-major [row][granule16B], 16 granules/row.
// Granule (row, g) at slot s = g ^ ((row>>2) & 7).
//  - cp.async: half-warp per row -> 16 distinct slots, 256B dense gmem read.
//  - store-phase scalar LDS: banks 4*(c4^r4)+dd all distinct per warp.
//  - STG.128 streaming (__stcs): each 8-lane octet writes 128B contiguous,
//    keeps the 41 MB x table resident in L2 against the 205 MB write stream.
__device__ __forceinline__ void issue_tile(const float4* __restrict__ x4,
                                           const int* __restrict__ idx,
                                           float* __restrict__ buf,
                                           int r0, int c0q, int hw, int g)
{
    #pragma unroll
    for (int i = 0; i < 2; i++) {
        const int row  = 16 * i + hw;                // 0..31, half-warp uniform
        const int srow = __ldg(&idx[r0 + row]);      // broadcast
        const int s    = g ^ ((row >> 2) & 7);       // swizzled granule slot
        const float4* src = &x4[(size_t)srow * (N_CELL / 4) + c0q + g];
        unsigned dst = (unsigned)__cvta_generic_to_shared(&buf[row * TILE_C + 4 * s]);
        asm volatile("cp.async.cg.shared.global [%0], [%1], 16;\n"
                     :: "r"(dst), "l"(src));
    }
    asm volatile("cp.async.commit_group;\n");
}

__global__ __launch_bounds__(256, 8)
void celltype_scale_transpose_v7(const float4* __restrict__ x4,
                                 const float*  __restrict__ w,
                                 const int*    __restrict__ idx,
                                 float*        __restrict__ out)
{
    __shared__ float buf[STAGES][TILE_R * TILE_C];   // 3 x 8 KB = 24 KB

    const int rbase = blockIdx.x * (TILE_R * NITER); // 625 groups of 160 rows
    const int c0    = blockIdx.y * TILE_C;           // 8 c-tiles
    const int c0q   = c0 >> 2;
    const int tid   = threadIdx.x;
    const int hw    = tid >> 4;                      // half-warp id 0..15
    const int g     = tid & 15;                      // granule 0..15

    // Store-phase invariants:
    const int r4   = tid & 7;                        // r-granule 0..7
    const int chi  = tid >> 3;                       // c base 0..31
    const int c4g0 = chi >> 2;
    const int dd   = chi & 3;

    // Prologue: two tiles in flight.
    issue_tile(x4, idx, buf[0], rbase,          c0q, hw, g);
    issue_tile(x4, idx, buf[1], rbase + TILE_R, c0q, hw, g);

    #pragma unroll
    for (int t = 0; t < NITER; t++) {
        const int r0 = rbase + t * TILE_R;

        // Wait for tile t's group. Pending at this point: {t, t+1} (or {t}).
        if (t + 1 < NITER) asm volatile("cp.async.wait_group 1;\n");
        else               asm volatile("cp.async.wait_group 0;\n");
        // Single barrier: makes tile t visible to all threads AND guarantees
        // everyone finished reading tile t-1 (the buffer tile t+2 overwrites).
        __syncthreads();

        // Kick off tile t+2 before consuming t: overlaps its gathered reads
        // with this iteration's store stream.
        if (t + 2 < NITER)
            issue_tile(x4, idx, buf[(t + 2) % STAGES], r0 + 2 * TILE_R, c0q, hw, g);

        // ---- scale + transpose-store from buf[t % STAGES] ----
        const float* b  = buf[t % STAGES] + 4 * r4 * TILE_C + dd;  // rows 4r4..+3
        const float wv  = w[(unsigned)(r0 + 4 * r4) / M_PER_CT];   // 4-aligned
        float* outb = out + (size_t)(c0 + chi) * R_TOTAL + r0 + 4 * r4;

        #pragma unroll
        for (int i = 0; i < 2; i++) {
            const int s = ((c4g0 + 8 * i) ^ r4) * 4;  // swizzled granule offset
            float4 v;
            v.x = b[0 * TILE_C + s] * wv;
            v.y = b[1 * TILE_C + s] * wv;
            v.z = b[2 * TILE_C + s] * wv;
            v.w = b[3 * TILE_C + s] * wv;
            __stcs((float4*)(outb + (size_t)(32 * i) * R_TOTAL), v);
        }
        // No second barrier: next iteration's post-wait __syncthreads covers
        // buffer-reuse safety (3-stage ring).
    }
}

extern "C" void kernel_launch(void* const* d_in, const int* in_sizes, int n_in,
                              void* d_out, int out_size)
{
    const float* x   = nullptr;
    const float* w   = nullptr;
    const int*   idx = nullptr;
    for (int i = 0; i < n_in; i++) {
        if (in_sizes[i] == N_FEATURE * N_CELL)      x   = (const float*)d_in[i];
        else if (in_sizes[i] == N_CT)               w   = (const float*)d_in[i];
        else if (in_sizes[i] == R_TOTAL)            idx = (const int*)d_in[i];
    }
    float* out = (float*)d_out;

    dim3 grid(R_TOTAL / (TILE_R * NITER), N_CELL / TILE_C);   // (625, 8)
    celltype_scale_transpose_v7<<<grid, 256>>>((const float4*)x, w, idx, out);
}